// round 1
// baseline (speedup 1.0000x reference)
#include <cuda_runtime.h>
#include <math.h>

#define BATCH   128
#define DD      128      // D
#define HH      256      // H
#define NBLK_C  256
#define THREADS 256
#define RBMAX   32
#define SEC     (BATCH*NBLK_C)   // 32768 elements per output section

// Scratch (device globals: no allocation allowed in kernel_launch)
// E levels 0..8: level l has 2^l rows of D floats, base row = (1<<l)-1 (511 rows total)
__device__ float g_E[BATCH * 511 * DD];
__device__ int   g_X[BATCH * 511];     // hard-bit vectors per level, same base offsets
__device__ int   g_U1H[BATCH * 256];   // u1h hold per level, base = (1<<(l-1))-1
__device__ int   g_fenc[BATCH * NBLK_C];

struct Ctx {
    float* Eb; int* Xb; int* U1Hb;
    float* zs; float* hs;
    const float* E_lab;
    const float* Wc1; const float* bc1; const float* Wc2; const float* bc2;
    const float* Wb1; const float* bb1; const float* Wb2; const float* bb2;
    const float* Wl;  float bl;
    const float* r_in;
    float* u_out; float* p_out;
    int b;
};

// Two-layer MLP on RB rows already assembled in zs (row stride 384).
// Layer1: thread t -> hidden col t (H=256). Layer2: split-K, c = t&127, kh = t>>7.
template<int RB>
__device__ __forceinline__ void mlp_chunk(int INW, float* zs, float* hs,
    const float* __restrict__ W1, const float* __restrict__ b1,
    const float* __restrict__ W2, const float* __restrict__ b2,
    float* __restrict__ Eout)
{
    const int t = threadIdx.x;
    float acc[RB];
    {
        float bv = __ldg(&b1[t]);
        #pragma unroll
        for (int r = 0; r < RB; r++) acc[r] = bv;
    }
    for (int k = 0; k < INW; k++) {
        float w = __ldg(&W1[k * HH + t]);
        #pragma unroll
        for (int r = 0; r < RB; r++) acc[r] = fmaf(zs[r * 384 + k], w, acc[r]);
    }
    #pragma unroll
    for (int r = 0; r < RB; r++) hs[r * HH + t] = fmaxf(acc[r], 0.0f);
    __syncthreads();

    const int c  = t & (DD - 1);
    const int kh = t >> 7;
    float a2[RB];
    #pragma unroll
    for (int r = 0; r < RB; r++) a2[r] = 0.0f;
    for (int k2 = 0; k2 < HH / 2; k2++) {
        int k = kh * (HH / 2) + k2;
        float w = __ldg(&W2[k * DD + c]);
        #pragma unroll
        for (int r = 0; r < RB; r++) a2[r] = fmaf(hs[r * HH + k], w, a2[r]);
    }
    // zs no longer needed -> reuse as partial buffer (RB*256 <= RB*384)
    float* ps = zs;
    #pragma unroll
    for (int r = 0; r < RB; r++) ps[r * HH + t] = a2[r];
    __syncthreads();
    if (t < DD) {
        float b2v = __ldg(&b2[t]);
        #pragma unroll
        for (int r = 0; r < RB; r++)
            Eout[r * DD + t] = ps[r * HH + t] + ps[r * HH + t + DD] + b2v;
    }
    __syncthreads();
}

// Runs check (u1h==nullptr) or bit MLP over R rows of level-l input Ein.
// check input row i = [e[2i], e[2i+1]] = Ein[i*256 .. i*256+255] (rows contiguous).
// bit adds E_lab[u1h[i]] as the third 128-chunk.
__device__ void run_mlp(Ctx& c, int R, const float* Ein, const int* u1h, float* Eout)
{
    const bool isBit = (u1h != nullptr);
    const float* W1 = isBit ? c.Wb1 : c.Wc1;
    const float* b1 = isBit ? c.bb1 : c.bc1;
    const float* W2 = isBit ? c.Wb2 : c.Wc2;
    const float* b2 = isBit ? c.bb2 : c.bc2;
    const int INW = isBit ? 384 : 256;
    int done = 0;
    while (done < R) {
        int rbc = R - done; if (rbc > RBMAX) rbc = RBMAX;
        __syncthreads();
        int total = rbc * INW;
        for (int idx = threadIdx.x; idx < total; idx += THREADS) {
            int r = idx / INW;
            int k = idx - r * INW;
            int row = done + r;
            float v;
            if (k < 256) v = Ein[row * 256 + k];
            else         v = c.E_lab[u1h[row] * DD + (k - 256)];
            c.zs[r * 384 + k] = v;
        }
        __syncthreads();
        float* Eo = Eout + done * DD;
        switch (rbc) {
            case 32: mlp_chunk<32>(INW, c.zs, c.hs, W1, b1, W2, b2, Eo); break;
            case 16: mlp_chunk<16>(INW, c.zs, c.hs, W1, b1, W2, b2, Eo); break;
            case 8:  mlp_chunk<8 >(INW, c.zs, c.hs, W1, b1, W2, b2, Eo); break;
            case 4:  mlp_chunk<4 >(INW, c.zs, c.hs, W1, b1, W2, b2, Eo); break;
            case 2:  mlp_chunk<2 >(INW, c.zs, c.hs, W1, b1, W2, b2, Eo); break;
            default: mlp_chunk<1 >(INW, c.zs, c.hs, W1, b1, W2, b2, Eo); break;
        }
        done += rbc;
    }
}

__device__ __forceinline__ void check_stage(Ctx& c, int l)
{
    int half = 1 << (l - 1);
    const float* Ein = c.Eb + ((1 << l) - 1) * DD;
    float* Eout = c.Eb + ((1 << (l - 1)) - 1) * DD;
    run_mlp(c, half, Ein, nullptr, Eout);
}

__device__ __forceinline__ void bit_stage(Ctx& c, int l)
{
    int half = 1 << (l - 1);
    const float* Ein = c.Eb + ((1 << l) - 1) * DD;
    float* Eout = c.Eb + ((1 << (l - 1)) - 1) * DD;
    int* u1h = c.U1Hb + ((1 << (l - 1)) - 1);
    int* Xlm = c.Xb + ((1 << (l - 1)) - 1);
    // save left child's hard bits (left child's X will be overwritten by right)
    __syncthreads();
    for (int i = threadIdx.x; i < half; i += THREADS) u1h[i] = Xlm[i];
    __syncthreads();
    run_mlp(c, half, Ein, u1h, Eout);
}

__device__ __forceinline__ void combine_stage(Ctx& c, int l)
{
    int half = 1 << (l - 1);
    int* u1h = c.U1Hb + ((1 << (l - 1)) - 1);
    int* Xlm = c.Xb + ((1 << (l - 1)) - 1);
    int* Xl  = c.Xb + ((1 << l) - 1);
    __syncthreads();
    for (int i = threadIdx.x; i < half; i += THREADS) {
        int u2 = Xlm[i];
        Xl[2 * i]     = u1h[i] ^ u2;
        Xl[2 * i + 1] = u2;
    }
    __syncthreads();
}

__device__ __forceinline__ void leaf_node(Ctx& c, int leafIdx)
{
    __syncthreads();
    int t = threadIdx.x;
    if (t < 32) {
        const float* e = c.Eb;  // level-0 base row = 0
        float s = 0.0f;
        for (int k = t; k < DD; k += 32) s = fmaf(e[k], __ldg(&c.Wl[k]), s);
        #pragma unroll
        for (int o = 16; o > 0; o >>= 1) s += __shfl_xor_sync(0xffffffffu, s, o);
        if (t == 0) {
            float p  = 1.0f / (1.0f + expf(-(s + c.bl)));
            float rv = __ldg(&c.r_in[c.b * NBLK_C + leafIdx]);
            int f  = g_fenc[c.b * NBLK_C + leafIdx];
            int hd = (rv > p) ? 1 : 0;
            int x  = ((f == 2) || (fabsf(p - 0.5f) > 0.25f)) ? hd : f;
            c.Xb[0] = x;
            c.u_out[c.b * NBLK_C + leafIdx] = (float)x;
            c.p_out[c.b * NBLK_C + leafIdx] = p;
        }
    }
    __syncthreads();
}

__global__ void __launch_bounds__(THREADS)
sc_main(const float* r_in, const float* E_lab,
        const float* Wc1, const float* bc1, const float* Wc2, const float* bc2,
        const float* Wb1, const float* bb1, const float* Wb2, const float* bb2,
        const float* Wl, const float* blp, float* out)
{
    extern __shared__ float sm[];
    Ctx c;
    c.zs = sm;
    c.hs = sm + RBMAX * 384;
    c.b = blockIdx.x;
    c.Eb   = g_E   + c.b * 511 * DD;
    c.Xb   = g_X   + c.b * 511;
    c.U1Hb = g_U1H + c.b * 256;
    c.E_lab = E_lab;
    c.Wc1 = Wc1; c.bc1 = bc1; c.Wc2 = Wc2; c.bc2 = bc2;
    c.Wb1 = Wb1; c.bb1 = bb1; c.Wb2 = Wb2; c.bb2 = bb2;
    c.Wl = Wl; c.bl = __ldg(&blp[0]);
    c.r_in  = r_in;
    c.u_out = out + 2 * SEC;
    c.p_out = out + 3 * SEC;

    // Iterative DFS (matches recursion: check, left, bit, right, combine)
    for (int l = 8; l >= 1; l--) check_stage(c, l);      // initial descent
    for (int i = 0; i < NBLK_C; i++) {
        leaf_node(c, i);
        if (i == NBLK_C - 1) break;
        int l = 1;
        while ((i >> (l - 1)) & 1) { combine_stage(c, l); l++; }
        bit_stage(c, l);                                  // we were the left child at level l
        for (int ld = l - 1; ld >= 1; ld--) check_stage(c, ld);
    }
    for (int l = 1; l <= 8; l++) combine_stage(c, l);     // final unwinding (leaf 255 all-right)

    // write x = X at level 8
    int* X8 = c.Xb + 255;
    for (int i = threadIdx.x; i < NBLK_C; i += THREADS)
        out[c.b * NBLK_C + i] = (float)X8[i];
}

// Setup: fenc, f-output, r-output copy, E level-8 init (= E_obs[2] everywhere)
__global__ void sc_setup(const int* info_bits, const float* r_in, const int* info_set,
                         const float* E_obs, float* out)
{
    int b = blockIdx.x, t = threadIdx.x;
    for (int j = t; j < NBLK_C; j += blockDim.x) {
        g_fenc[b * NBLK_C + j] = 2;
        out[1 * SEC + b * NBLK_C + j] = 1.0f;                       // f = 1
        out[4 * SEC + b * NBLK_C + j] = r_in[b * NBLK_C + j];       // r copy
    }
    __syncthreads();
    for (int k = t; k < 128; k += blockDim.x) {
        int pos = info_set[k];
        g_fenc[b * NBLK_C + pos] = info_bits[b * 128 + k];
        out[1 * SEC + b * NBLK_C + pos] = 2.0f;                     // f = 2 at info positions
    }
    // E level 8 init: rows 255..510, every row = E_obs[2]
    for (int idx = t; idx < 256 * DD; idx += blockDim.x) {
        int i = idx >> 7, k = idx & (DD - 1);
        g_E[b * 511 * DD + (255 + i) * DD + k] = E_obs[2 * DD + k];
    }
}

extern "C" void kernel_launch(void* const* d_in, const int* in_sizes, int n_in,
                              void* d_out, int out_size)
{
    const int*   info_bits = (const int*)  d_in[0];
    const float* r_in      = (const float*)d_in[1];
    const int*   info_set  = (const int*)  d_in[2];
    const float* E_obs     = (const float*)d_in[3];
    const float* E_lab     = (const float*)d_in[4];
    const float* Wc1 = (const float*)d_in[5];
    const float* bc1 = (const float*)d_in[6];
    const float* Wc2 = (const float*)d_in[7];
    const float* bc2 = (const float*)d_in[8];
    const float* Wb1 = (const float*)d_in[9];
    const float* bb1 = (const float*)d_in[10];
    const float* Wb2 = (const float*)d_in[11];
    const float* bb2 = (const float*)d_in[12];
    const float* Wl  = (const float*)d_in[13];
    const float* bl  = (const float*)d_in[14];
    float* out = (float*)d_out;

    const int smem = (RBMAX * 384 + RBMAX * HH) * sizeof(float);   // 80 KB
    cudaFuncSetAttribute(sc_main, cudaFuncAttributeMaxDynamicSharedMemorySize, smem);

    sc_setup<<<BATCH, THREADS>>>(info_bits, r_in, info_set, E_obs, out);
    sc_main<<<BATCH, THREADS, smem>>>(r_in, E_lab,
                                      Wc1, bc1, Wc2, bc2,
                                      Wb1, bb1, Wb2, bb2,
                                      Wl, bl, out);
}

// round 2
// speedup vs baseline: 1.6832x; 1.6832x over previous
#include <cuda_runtime.h>
#include <math.h>

#define BATCH   128
#define DD      128
#define HH      256
#define NBLK_C  256
#define THREADS 1024
#define RBMAX   32
#define SEC     (BATCH*NBLK_C)

// ---- device scratch (no allocations allowed) ----
// E levels 0..8: level l has 2^l rows of D floats, base row = (1<<l)-1
__device__ float g_E[BATCH * 511 * DD];
__device__ float g_BP[BATCH * 255 * HH];   // bitnode layer-1 partials, base (1<<(l-1))-1
__device__ int   g_X[BATCH * 511];
__device__ int   g_U1H[BATCH * 256];
__device__ int   g_fenc[BATCH * NBLK_C];
// fused layer-1 weights: Wf[k][c] = (c<256 ? Wc1[k][c] : Wb1[k][c-256]), k<256
__device__ float g_Wf[256 * 512];
__device__ float g_bf[512];                // [bc1 | bb1]
__device__ float g_emb[2 * HH];            // E_lab[u] @ Wb1[256:384,:]

struct Ctx {
    float* Eb; float* BPb; int* Xb; int* U1Hb;
    float* zs; float* hs; float* red;
    const float* Wc2; const float* bc2;
    const float* Wb2; const float* bb2;
    const float* Wl;  float bl;
    const float* r_in;
    float* u_out; float* p_out;
    int b;
};

// ---------- fused layer 1: [RB x 256] @ [256 x 512] ----------
// cols 0..255 -> check hidden (relu into hs), cols 256..511 -> bit partial (to global bp)
template<int RB>
__device__ __forceinline__ void layer1_fused(const float* zs, float* hs, float* bp, float* red)
{
    const int t = threadIdx.x;
    if constexpr (RB >= 2) {
        constexpr int NR = RB / 2;
        const int col = t & 511;
        const int rg  = t >> 9;           // 0 or 1; constant within warp
        float acc[NR];
        #pragma unroll
        for (int r = 0; r < NR; r++) acc[r] = 0.0f;
        #pragma unroll 4
        for (int k = 0; k < 256; k++) {
            float w = __ldg(&g_Wf[k * 512 + col]);
            #pragma unroll
            for (int r = 0; r < NR; r++)
                acc[r] = fmaf(zs[(rg + 2 * r) * 256 + k], w, acc[r]);
        }
        float b = g_bf[col];
        #pragma unroll
        for (int r = 0; r < NR; r++) {
            int row = rg + 2 * r;
            float v = acc[r] + b;
            if (col < 256) hs[row * 256 + col] = fmaxf(v, 0.0f);
            else           bp[row * HH + (col - 256)] = v;
        }
    } else {
        // RB == 1: split-K 2-way so all 1024 threads stream weights
        const int col  = t & 511;
        const int part = t >> 9;
        const int k0   = part * 128;
        float acc = 0.0f;
        #pragma unroll 8
        for (int kk = 0; kk < 128; kk++) {
            int k = k0 + kk;
            acc = fmaf(zs[k], __ldg(&g_Wf[k * 512 + col]), acc);
        }
        red[part * 512 + col] = acc;
        __syncthreads();
        if (t < 512) {
            float v = red[t] + red[512 + t] + g_bf[t];
            if (t < 256) hs[t] = fmaxf(v, 0.0f);
            else         bp[t - 256] = v;
        }
    }
}

// ---------- layer 2: [RB x 256] @ [256 x 128] + b ----------
template<int RB>
__device__ __forceinline__ void layer2(const float* hs, const float* __restrict__ W2,
                                       const float* __restrict__ b2, float* Eout, float* red)
{
    const int t = threadIdx.x;
    const int col = t & 127;
    if constexpr (RB >= 8) {
        constexpr int NR = RB / 8;
        const int rg = t >> 7;            // 0..7, constant within warp
        float acc[NR];
        #pragma unroll
        for (int r = 0; r < NR; r++) acc[r] = 0.0f;
        #pragma unroll 4
        for (int k = 0; k < 256; k++) {
            float w = __ldg(&W2[k * 128 + col]);
            #pragma unroll
            for (int r = 0; r < NR; r++)
                acc[r] = fmaf(hs[(rg + 8 * r) * 256 + k], w, acc[r]);
        }
        float b = __ldg(&b2[col]);
        #pragma unroll
        for (int r = 0; r < NR; r++)
            Eout[(rg + 8 * r) * 128 + col] = acc[r] + b;
    } else {
        constexpr int KP = 8 / RB;        // k partitions
        constexpr int KL = 256 / KP;      // k per partition
        const int g    = t >> 7;          // 0..7 = part*RB + r
        const int r    = g & (RB - 1);
        const int part = g / RB;
        const int k0   = part * KL;
        float acc = 0.0f;
        #pragma unroll 8
        for (int kk = 0; kk < KL; kk++) {
            int k = k0 + kk;
            acc = fmaf(hs[r * 256 + k], __ldg(&W2[k * 128 + col]), acc);
        }
        red[g * 128 + col] = acc;
        __syncthreads();
        if (t < RB * 128) {
            int r2 = t >> 7;
            float s = __ldg(&b2[col]);
            #pragma unroll
            for (int p = 0; p < KP; p++) s += red[(p * RB + r2) * 128 + col];
            Eout[r2 * 128 + col] = s;
        }
    }
}

#define L1_DISPATCH(RB) layer1_fused<RB>(c.zs, c.hs, BPl + done * HH, c.red)
#define L2_DISPATCH(RB, W2, B2) layer2<RB>(c.hs, W2, B2, Eout + done * DD, c.red)

// check stage at level l: also emits bit partials for this node
__device__ void check_stage(Ctx& c, int l)
{
    const int half = 1 << (l - 1);
    const float* Ein = c.Eb + ((1 << l) - 1) * DD;
    float* Eout = c.Eb + ((1 << (l - 1)) - 1) * DD;
    float* BPl  = c.BPb + ((1 << (l - 1)) - 1) * HH;
    int done = 0;
    while (done < half) {
        int rbc = half - done; if (rbc > RBMAX) rbc = RBMAX;
        __syncthreads();
        // stage inputs (contiguous): rbc*256 floats
        {
            const float4* src = (const float4*)(Ein + done * 256);
            float4* dst = (float4*)c.zs;
            for (int i = threadIdx.x; i < rbc * 64; i += THREADS) dst[i] = src[i];
        }
        __syncthreads();
        switch (rbc) {
            case 32: L1_DISPATCH(32); break;
            case 16: L1_DISPATCH(16); break;
            case 8:  L1_DISPATCH(8);  break;
            case 4:  L1_DISPATCH(4);  break;
            case 2:  L1_DISPATCH(2);  break;
            default: L1_DISPATCH(1);  break;
        }
        __syncthreads();
        switch (rbc) {
            case 32: L2_DISPATCH(32, c.Wc2, c.bc2); break;
            case 16: L2_DISPATCH(16, c.Wc2, c.bc2); break;
            case 8:  L2_DISPATCH(8,  c.Wc2, c.bc2); break;
            case 4:  L2_DISPATCH(4,  c.Wc2, c.bc2); break;
            case 2:  L2_DISPATCH(2,  c.Wc2, c.bc2); break;
            default: L2_DISPATCH(1,  c.Wc2, c.bc2); break;
        }
        done += rbc;
    }
    __syncthreads();
}

// bit stage at level l: hidden = relu(bp + emb[u1h]); then layer 2
__device__ void bit_stage(Ctx& c, int l)
{
    const int half = 1 << (l - 1);
    float* Eout = c.Eb + ((1 << (l - 1)) - 1) * DD;
    float* BPl  = c.BPb + ((1 << (l - 1)) - 1) * HH;
    int* u1h = c.U1Hb + ((1 << (l - 1)) - 1);
    int* Xlm = c.Xb + ((1 << (l - 1)) - 1);
    __syncthreads();
    for (int i = threadIdx.x; i < half; i += THREADS) u1h[i] = Xlm[i];
    __syncthreads();
    int done = 0;
    while (done < half) {
        int rbc = half - done; if (rbc > RBMAX) rbc = RBMAX;
        for (int idx = threadIdx.x; idx < rbc * 256; idx += THREADS) {
            int r = idx >> 8, j = idx & 255;
            int row = done + r;
            c.hs[r * 256 + j] = fmaxf(BPl[row * HH + j] + g_emb[u1h[row] * HH + j], 0.0f);
        }
        __syncthreads();
        switch (rbc) {
            case 32: L2_DISPATCH(32, c.Wb2, c.bb2); break;
            case 16: L2_DISPATCH(16, c.Wb2, c.bb2); break;
            case 8:  L2_DISPATCH(8,  c.Wb2, c.bb2); break;
            case 4:  L2_DISPATCH(4,  c.Wb2, c.bb2); break;
            case 2:  L2_DISPATCH(2,  c.Wb2, c.bb2); break;
            default: L2_DISPATCH(1,  c.Wb2, c.bb2); break;
        }
        __syncthreads();
        done += rbc;
    }
}

__device__ __forceinline__ void combine_stage(Ctx& c, int l)
{
    int half = 1 << (l - 1);
    int* u1h = c.U1Hb + ((1 << (l - 1)) - 1);
    int* Xlm = c.Xb + ((1 << (l - 1)) - 1);
    int* Xl  = c.Xb + ((1 << l) - 1);
    __syncthreads();
    for (int i = threadIdx.x; i < half; i += THREADS) {
        int u2 = Xlm[i];
        Xl[2 * i]     = u1h[i] ^ u2;
        Xl[2 * i + 1] = u2;
    }
    __syncthreads();
}

__device__ __forceinline__ void leaf_node(Ctx& c, int leafIdx)
{
    __syncthreads();
    int t = threadIdx.x;
    if (t < 32) {
        const float* e = c.Eb;   // level-0 row
        float s = 0.0f;
        for (int k = t; k < DD; k += 32) s = fmaf(e[k], __ldg(&c.Wl[k]), s);
        #pragma unroll
        for (int o = 16; o > 0; o >>= 1) s += __shfl_xor_sync(0xffffffffu, s, o);
        if (t == 0) {
            float p  = 1.0f / (1.0f + expf(-(s + c.bl)));
            float rv = __ldg(&c.r_in[c.b * NBLK_C + leafIdx]);
            int f  = g_fenc[c.b * NBLK_C + leafIdx];
            int hd = (rv > p) ? 1 : 0;
            int x  = ((f == 2) || (fabsf(p - 0.5f) > 0.25f)) ? hd : f;
            c.Xb[0] = x;
            c.u_out[c.b * NBLK_C + leafIdx] = (float)x;
            c.p_out[c.b * NBLK_C + leafIdx] = p;
        }
    }
    __syncthreads();
}

__global__ void __launch_bounds__(THREADS, 1)
sc_main(const float* r_in,
        const float* Wc2, const float* bc2,
        const float* Wb2, const float* bb2,
        const float* Wl, const float* blp, float* out)
{
    extern __shared__ float sm[];
    Ctx c;
    c.zs  = sm;
    c.hs  = sm + RBMAX * 256;
    c.red = sm + 2 * RBMAX * 256;
    c.b = blockIdx.x;
    c.Eb   = g_E   + c.b * 511 * DD;
    c.BPb  = g_BP  + c.b * 255 * HH;
    c.Xb   = g_X   + c.b * 511;
    c.U1Hb = g_U1H + c.b * 256;
    c.Wc2 = Wc2; c.bc2 = bc2;
    c.Wb2 = Wb2; c.bb2 = bb2;
    c.Wl = Wl; c.bl = __ldg(&blp[0]);
    c.r_in  = r_in;
    c.u_out = out + 2 * SEC;
    c.p_out = out + 3 * SEC;

    // iterative DFS: check, left, bit, right, combine
    for (int l = 8; l >= 1; l--) check_stage(c, l);
    for (int i = 0; i < NBLK_C; i++) {
        leaf_node(c, i);
        if (i == NBLK_C - 1) break;
        int l = 1;
        while ((i >> (l - 1)) & 1) { combine_stage(c, l); l++; }
        bit_stage(c, l);
        for (int ld = l - 1; ld >= 1; ld--) check_stage(c, ld);
    }
    for (int l = 1; l <= 8; l++) combine_stage(c, l);

    int* X8 = c.Xb + 255;
    for (int i = threadIdx.x; i < NBLK_C; i += THREADS)
        out[c.b * NBLK_C + i] = (float)X8[i];
}

// ---- setup: per-batch init ----
__global__ void sc_setup(const int* info_bits, const float* r_in, const int* info_set,
                         const float* E_obs, float* out)
{
    int b = blockIdx.x, t = threadIdx.x;
    for (int j = t; j < NBLK_C; j += blockDim.x) {
        g_fenc[b * NBLK_C + j] = 2;
        out[1 * SEC + b * NBLK_C + j] = 1.0f;
        out[4 * SEC + b * NBLK_C + j] = r_in[b * NBLK_C + j];
    }
    __syncthreads();
    for (int k = t; k < 128; k += blockDim.x) {
        int pos = info_set[k];
        g_fenc[b * NBLK_C + pos] = info_bits[b * 128 + k];
        out[1 * SEC + b * NBLK_C + pos] = 2.0f;
    }
    for (int idx = t; idx < 256 * DD; idx += blockDim.x) {
        int i = idx >> 7, k = idx & (DD - 1);
        g_E[b * 511 * DD + (255 + i) * DD + k] = E_obs[2 * DD + k];
    }
}

// ---- setup: fused weights + label-embedding layer-1 precompute ----
__global__ void sc_prep(const float* Wc1, const float* bc1,
                        const float* Wb1, const float* bb1,
                        const float* E_lab)
{
    int t = threadIdx.x;
    for (int idx = t; idx < 256 * 512; idx += blockDim.x) {
        int k = idx >> 9, cc = idx & 511;
        g_Wf[idx] = (cc < 256) ? Wc1[k * 256 + cc] : Wb1[k * 256 + (cc - 256)];
    }
    if (t < 512) g_bf[t] = (t < 256) ? bc1[t] : bb1[t - 256];
    if (t < 512) {
        int u = t >> 8, j = t & 255;
        float s = 0.0f;
        for (int d = 0; d < 128; d++)
            s += E_lab[u * 128 + d] * Wb1[(256 + d) * 256 + j];
        g_emb[u * HH + j] = s;
    }
}

extern "C" void kernel_launch(void* const* d_in, const int* in_sizes, int n_in,
                              void* d_out, int out_size)
{
    const int*   info_bits = (const int*)  d_in[0];
    const float* r_in      = (const float*)d_in[1];
    const int*   info_set  = (const int*)  d_in[2];
    const float* E_obs     = (const float*)d_in[3];
    const float* E_lab     = (const float*)d_in[4];
    const float* Wc1 = (const float*)d_in[5];
    const float* bc1 = (const float*)d_in[6];
    const float* Wc2 = (const float*)d_in[7];
    const float* bc2 = (const float*)d_in[8];
    const float* Wb1 = (const float*)d_in[9];
    const float* bb1 = (const float*)d_in[10];
    const float* Wb2 = (const float*)d_in[11];
    const float* bb2 = (const float*)d_in[12];
    const float* Wl  = (const float*)d_in[13];
    const float* bl  = (const float*)d_in[14];
    float* out = (float*)d_out;

    const int smem = (2 * RBMAX * 256 + 1024) * sizeof(float);   // 68 KB
    cudaFuncSetAttribute(sc_main, cudaFuncAttributeMaxDynamicSharedMemorySize, smem);

    sc_prep<<<1, 512>>>(Wc1, bc1, Wb1, bb1, E_lab);
    sc_setup<<<BATCH, 256>>>(info_bits, r_in, info_set, E_obs, out);
    sc_main<<<BATCH, THREADS, smem>>>(r_in, Wc2, bc2, Wb2, bb2, Wl, bl, out);
}

// round 3
// speedup vs baseline: 2.3431x; 1.3921x over previous
#include <cuda_runtime.h>
#include <math.h>

#define BATCH   128
#define DD      128
#define HH      256
#define NBLK_C  256
#define THREADS 1024
#define RBMAX   32
#define SEC     (BATCH*NBLK_C)

typedef unsigned long long u64;

// ---- device scratch (no allocations allowed) ----
__device__ __align__(16) float g_E[BATCH * 511 * DD];
__device__ __align__(16) float g_BP[BATCH * 255 * HH];
__device__ int   g_X[BATCH * 511];
__device__ int   g_U1H[BATCH * 256];
__device__ int   g_fenc[BATCH * NBLK_C];
__device__ __align__(16) float g_Wf[256 * 512];   // [Wc1 | Wb1(top 256 rows)] col-fused
__device__ __align__(16) float g_bf[512];         // [bc1 | bb1]
__device__ __align__(16) float g_emb[2 * HH];     // E_lab[u] @ Wb1[256:384,:]
__device__ __align__(16) float g_w2l[512];        // [Wc2@Wl | Wb2@Wl]
__device__ float g_pbias[2];                      // [bc2@Wl+bl, bb2@Wl+bl]

// ---- f32x2 helpers ----
__device__ __forceinline__ void fma2(u64& acc, u64 a, u64 b) {
    asm("fma.rn.f32x2 %0, %1, %2, %0;" : "+l"(acc) : "l"(a), "l"(b));
}
__device__ __forceinline__ u64 pk2(float x, float y) {
    u64 r; asm("mov.b64 %0, {%1, %2};" : "=l"(r) : "f"(x), "f"(y)); return r;
}
__device__ __forceinline__ float2 upk(u64 v) {
    float2 r; asm("mov.b64 {%0, %1}, %2;" : "=f"(r.x), "=f"(r.y) : "l"(v)); return r;
}

struct Ctx {
    float* Eb; float* BPb; int* Xb; int* U1Hb;
    u64* hs; u64* zs; float* red; float* nh; float* nbp; int* nx;
    const float* Wc2; const float* bc2;
    const float* Wb2; const float* bb2;
    const float* r_in;
    float* u_out; float* p_out;
    int b;
};

// ---------- layer 1 fused: [RB x 256] @ [256 x 512] ----------
// cols 0..255 -> relu -> hs (dup'd f32x2 pairs); cols 256..511 -> bp_out (global)
template<int RB>
__device__ void l1_chunk(const float* __restrict__ Ein, u64* zs, u64* hs,
                         float* __restrict__ bp_out, float* red)
{
    const int t = threadIdx.x;
    if constexpr (RB >= 8) {
        // stage acts, duplicated for f32x2
        for (int idx = t; idx < RB * 128; idx += THREADS) {
            float2 v = ((const float2*)Ein)[idx];
            ulonglong2 d; d.x = pk2(v.x, v.x); d.y = pk2(v.y, v.y);
            ((ulonglong2*)zs)[idx] = d;
        }
        __syncthreads();
        constexpr int NR = RB / 8;
        const int colq = t & 127;
        const int rg   = t >> 7;
        u64 acc[NR][2];
        #pragma unroll
        for (int r = 0; r < NR; r++) { acc[r][0] = 0ull; acc[r][1] = 0ull; }
        const ulonglong2* W = (const ulonglong2*)g_Wf + colq;
        #pragma unroll 2
        for (int k = 0; k < 256; k += 2) {
            ulonglong2 a2[NR];
            #pragma unroll
            for (int r = 0; r < NR; r++)
                a2[r] = *((const ulonglong2*)&zs[(rg + 8 * r) * 256 + k]);
            ulonglong2 w0 = __ldg(W + (size_t)k * 128);
            ulonglong2 w1 = __ldg(W + (size_t)(k + 1) * 128);
            #pragma unroll
            for (int r = 0; r < NR; r++) {
                fma2(acc[r][0], a2[r].x, w0.x); fma2(acc[r][1], a2[r].x, w0.y);
                fma2(acc[r][0], a2[r].y, w1.x); fma2(acc[r][1], a2[r].y, w1.y);
            }
        }
        const int col = colq * 4;
        float4 bias = *((const float4*)&g_bf[col]);
        #pragma unroll
        for (int r = 0; r < NR; r++) {
            int row = rg + 8 * r;
            float2 v0 = upk(acc[r][0]); float2 v1 = upk(acc[r][1]);
            float o0 = v0.x + bias.x, o1 = v0.y + bias.y;
            float o2 = v1.x + bias.z, o3 = v1.y + bias.w;
            if (col < 256) {
                float r0 = fmaxf(o0, 0.f), r1 = fmaxf(o1, 0.f);
                float r2 = fmaxf(o2, 0.f), r3 = fmaxf(o3, 0.f);
                ulonglong2 d0; d0.x = pk2(r0, r0); d0.y = pk2(r1, r1);
                ulonglong2 d1; d1.x = pk2(r2, r2); d1.y = pk2(r3, r3);
                *((ulonglong2*)&hs[row * 256 + col])     = d0;
                *((ulonglong2*)&hs[row * 256 + col + 2]) = d1;
            } else {
                *((float4*)&bp_out[row * HH + (col - 256)]) = make_float4(o0, o1, o2, o3);
            }
        }
        __syncthreads();
    } else {
        // RB = 2 or 4: split-K, acts direct from global
        constexpr int KP = 8 / RB;
        constexpr int KL = 256 / KP;
        const int colq = t & 127;
        const int g    = t >> 7;
        const int r    = g & (RB - 1);
        const int kp   = g / RB;
        const int k0   = kp * KL;
        const float* ac = Ein + r * 256;
        u64 acc0 = 0ull, acc1 = 0ull;
        const ulonglong2* W = (const ulonglong2*)g_Wf + colq;
        #pragma unroll 2
        for (int kb = 0; kb < KL; kb += 4) {
            float4 a4 = __ldg((const float4*)&ac[k0 + kb]);
            ulonglong2 w; u64 a;
            w = __ldg(W + (size_t)(k0 + kb + 0) * 128); a = pk2(a4.x, a4.x); fma2(acc0, a, w.x); fma2(acc1, a, w.y);
            w = __ldg(W + (size_t)(k0 + kb + 1) * 128); a = pk2(a4.y, a4.y); fma2(acc0, a, w.x); fma2(acc1, a, w.y);
            w = __ldg(W + (size_t)(k0 + kb + 2) * 128); a = pk2(a4.z, a4.z); fma2(acc0, a, w.x); fma2(acc1, a, w.y);
            w = __ldg(W + (size_t)(k0 + kb + 3) * 128); a = pk2(a4.w, a4.w); fma2(acc0, a, w.x); fma2(acc1, a, w.y);
        }
        float2 v0 = upk(acc0), v1 = upk(acc1);
        ((float4*)red)[g * 128 + colq] = make_float4(v0.x, v0.y, v1.x, v1.y);
        __syncthreads();
        for (int idx = t; idx < RB * 512; idx += THREADS) {
            int row = idx >> 9, col = idx & 511;
            float v = g_bf[col];
            #pragma unroll
            for (int q = 0; q < KP; q++) v += red[(q * RB + row) * 512 + col];
            if (col < 256) { float rl = fmaxf(v, 0.f); hs[row * 256 + col] = pk2(rl, rl); }
            else bp_out[row * HH + (col - 256)] = v;
        }
        __syncthreads();
    }
}

// ---------- layer 2: [RB x 256] @ [256 x 128] + b2 ----------
template<int RB>
__device__ void l2_chunk(const u64* hs, const float* __restrict__ W2,
                         const float* __restrict__ b2, float* __restrict__ Eout,
                         float* red)
{
    const int t = threadIdx.x;
    const int colq = t & 31;
    const int g    = t >> 5;
    const ulonglong2* W = (const ulonglong2*)W2 + colq;
    if constexpr (RB == 32) {
        const int row = g;
        u64 acc0 = 0ull, acc1 = 0ull;
        #pragma unroll 2
        for (int k = 0; k < 256; k += 2) {
            ulonglong2 a2 = *((const ulonglong2*)&hs[row * 256 + k]);
            ulonglong2 w0 = __ldg(W + (size_t)k * 32);
            ulonglong2 w1 = __ldg(W + (size_t)(k + 1) * 32);
            fma2(acc0, a2.x, w0.x); fma2(acc1, a2.x, w0.y);
            fma2(acc0, a2.y, w1.x); fma2(acc1, a2.y, w1.y);
        }
        float2 v0 = upk(acc0), v1 = upk(acc1);
        const int col = colq * 4;
        float4 bb = *((const float4*)&b2[col]);
        *((float4*)&Eout[row * 128 + col]) =
            make_float4(v0.x + bb.x, v0.y + bb.y, v1.x + bb.z, v1.y + bb.w);
        __syncthreads();
    } else {
        constexpr int KP = 32 / RB;
        constexpr int KL = 256 / KP;
        const int row = g & (RB - 1);
        const int kp  = g / RB;
        const int k0  = kp * KL;
        u64 acc0 = 0ull, acc1 = 0ull;
        #pragma unroll 2
        for (int k = k0; k < k0 + KL; k += 2) {
            ulonglong2 a2 = *((const ulonglong2*)&hs[row * 256 + k]);
            ulonglong2 w0 = __ldg(W + (size_t)k * 32);
            ulonglong2 w1 = __ldg(W + (size_t)(k + 1) * 32);
            fma2(acc0, a2.x, w0.x); fma2(acc1, a2.x, w0.y);
            fma2(acc0, a2.y, w1.x); fma2(acc1, a2.y, w1.y);
        }
        float2 v0 = upk(acc0), v1 = upk(acc1);
        ((float4*)red)[g * 32 + colq] = make_float4(v0.x, v0.y, v1.x, v1.y);
        __syncthreads();
        for (int idx = t; idx < RB * 128; idx += THREADS) {
            int row2 = idx >> 7, col = idx & 127;
            float v = __ldg(&b2[col]);
            #pragma unroll
            for (int q = 0; q < KP; q++) v += red[(q * RB + row2) * 128 + col];
            Eout[row2 * 128 + col] = v;
        }
        __syncthreads();
    }
}

__device__ void check_stage(Ctx& c, int l)
{
    const int half = 1 << (l - 1);
    const float* Ein = c.Eb + ((1 << l) - 1) * DD;
    float* Eout = c.Eb + ((1 << (l - 1)) - 1) * DD;
    float* BPl  = c.BPb + ((1 << (l - 1)) - 1) * HH;
    for (int done = 0; done < half; done += RBMAX) {
        int rbc = half - done; if (rbc > RBMAX) rbc = RBMAX;
        const float* ei = Ein + done * 256;
        float* eo = Eout + done * DD;
        float* bo = BPl + done * HH;
        switch (rbc) {
            case 32: l1_chunk<32>(ei, c.zs, c.hs, bo, c.red); l2_chunk<32>(c.hs, c.Wc2, c.bc2, eo, c.red); break;
            case 16: l1_chunk<16>(ei, c.zs, c.hs, bo, c.red); l2_chunk<16>(c.hs, c.Wc2, c.bc2, eo, c.red); break;
            case 8:  l1_chunk<8 >(ei, c.zs, c.hs, bo, c.red); l2_chunk<8 >(c.hs, c.Wc2, c.bc2, eo, c.red); break;
            case 4:  l1_chunk<4 >(ei, c.zs, c.hs, bo, c.red); l2_chunk<4 >(c.hs, c.Wc2, c.bc2, eo, c.red); break;
            default: l1_chunk<2 >(ei, c.zs, c.hs, bo, c.red); l2_chunk<2 >(c.hs, c.Wc2, c.bc2, eo, c.red); break;
        }
    }
}

__device__ void bit_stage(Ctx& c, int l)
{
    const int half = 1 << (l - 1);
    const int base = (1 << (l - 1)) - 1;
    float* Eout = c.Eb + base * DD;
    const float* BPl = c.BPb + base * HH;
    int* u1h = c.U1Hb + base;
    int* Xlm = c.Xb + base;
    __syncthreads();
    for (int i = threadIdx.x; i < half; i += THREADS) u1h[i] = Xlm[i];
    __syncthreads();
    for (int done = 0; done < half; done += RBMAX) {
        int rbc = half - done; if (rbc > RBMAX) rbc = RBMAX;
        for (int idx = threadIdx.x; idx < rbc * 256; idx += THREADS) {
            int row = idx >> 8, k = idx & 255;
            int u = u1h[done + row];
            float v = fmaxf(BPl[(done + row) * HH + k] + g_emb[u * HH + k], 0.f);
            c.hs[idx] = pk2(v, v);
        }
        __syncthreads();
        float* eo = Eout + done * DD;
        switch (rbc) {
            case 32: l2_chunk<32>(c.hs, c.Wb2, c.bb2, eo, c.red); break;
            case 16: l2_chunk<16>(c.hs, c.Wb2, c.bb2, eo, c.red); break;
            case 8:  l2_chunk<8 >(c.hs, c.Wb2, c.bb2, eo, c.red); break;
            case 4:  l2_chunk<4 >(c.hs, c.Wb2, c.bb2, eo, c.red); break;
            default: l2_chunk<2 >(c.hs, c.Wb2, c.bb2, eo, c.red); break;
        }
    }
}

__device__ __forceinline__ void combine_stage(Ctx& c, int l)
{
    int half = 1 << (l - 1);
    int* u1h = c.U1Hb + ((1 << (l - 1)) - 1);
    int* Xlm = c.Xb + ((1 << (l - 1)) - 1);
    int* Xl  = c.Xb + ((1 << l) - 1);
    __syncthreads();
    for (int i = threadIdx.x; i < half; i += THREADS) {
        int u2 = Xlm[i];
        Xl[2 * i]     = u1h[i] ^ u2;
        Xl[2 * i + 1] = u2;
    }
    __syncthreads();
}

// Fused level-1 node: check-L1 -> p_left -> left leaf -> bit-hidden -> p_right
// -> right leaf -> combine(1). No layer-2 GEMMs needed (dots vs W2@Wl).
__device__ void node1(Ctx& c, int n)
{
    const int t = threadIdx.x;
    const float* Ein = c.Eb + DD;   // level-1 array (2 rows) at base 1
    const int colq = t & 127;
    const int kp   = t >> 7;
    const int k0   = kp * 32;
    u64 acc0 = 0ull, acc1 = 0ull;
    const ulonglong2* W = (const ulonglong2*)g_Wf + colq;
    #pragma unroll
    for (int kb = 0; kb < 32; kb += 4) {
        float4 a4 = __ldg((const float4*)&Ein[k0 + kb]);
        ulonglong2 w; u64 a;
        w = __ldg(W + (size_t)(k0 + kb + 0) * 128); a = pk2(a4.x, a4.x); fma2(acc0, a, w.x); fma2(acc1, a, w.y);
        w = __ldg(W + (size_t)(k0 + kb + 1) * 128); a = pk2(a4.y, a4.y); fma2(acc0, a, w.x); fma2(acc1, a, w.y);
        w = __ldg(W + (size_t)(k0 + kb + 2) * 128); a = pk2(a4.z, a4.z); fma2(acc0, a, w.x); fma2(acc1, a, w.y);
        w = __ldg(W + (size_t)(k0 + kb + 3) * 128); a = pk2(a4.w, a4.w); fma2(acc0, a, w.x); fma2(acc1, a, w.y);
    }
    float2 v0 = upk(acc0), v1 = upk(acc1);
    ((float4*)c.red)[kp * 128 + colq] = make_float4(v0.x, v0.y, v1.x, v1.y);
    __syncthreads();
    if (t < 512) {
        float v = g_bf[t];
        #pragma unroll
        for (int q = 0; q < 8; q++) v += c.red[q * 512 + t];
        if (t < 256) c.nh[t] = fmaxf(v, 0.f);
        else c.nbp[t - 256] = v;
    }
    __syncthreads();
    if (t < 32) {
        float s = 0.f;
        #pragma unroll
        for (int j = 0; j < 8; j++) s = fmaf(c.nh[t + 32 * j], g_w2l[t + 32 * j], s);
        #pragma unroll
        for (int o = 16; o > 0; o >>= 1) s += __shfl_xor_sync(0xffffffffu, s, o);
        if (t == 0) {
            float p = 1.f / (1.f + expf(-(s + g_pbias[0])));
            int leaf = 2 * n;
            float rv = __ldg(&c.r_in[c.b * NBLK_C + leaf]);
            int f  = g_fenc[c.b * NBLK_C + leaf];
            int hd = (rv > p) ? 1 : 0;
            int x  = ((f == 2) || (fabsf(p - 0.5f) > 0.25f)) ? hd : f;
            *c.nx = x;
            c.u_out[c.b * NBLK_C + leaf] = (float)x;
            c.p_out[c.b * NBLK_C + leaf] = p;
        }
    }
    __syncthreads();
    int xL = *c.nx;
    if (t < 256)
        c.red[t] = fmaxf(c.nbp[t] + g_emb[xL * HH + t], 0.f) * g_w2l[256 + t];
    __syncthreads();
    if (t < 32) {
        float s = 0.f;
        #pragma unroll
        for (int j = 0; j < 8; j++) s += c.red[t + 32 * j];
        #pragma unroll
        for (int o = 16; o > 0; o >>= 1) s += __shfl_xor_sync(0xffffffffu, s, o);
        if (t == 0) {
            float p = 1.f / (1.f + expf(-(s + g_pbias[1])));
            int leaf = 2 * n + 1;
            float rv = __ldg(&c.r_in[c.b * NBLK_C + leaf]);
            int f  = g_fenc[c.b * NBLK_C + leaf];
            int hd = (rv > p) ? 1 : 0;
            int xR = ((f == 2) || (fabsf(p - 0.5f) > 0.25f)) ? hd : f;
            c.u_out[c.b * NBLK_C + leaf] = (float)xR;
            c.p_out[c.b * NBLK_C + leaf] = p;
            c.Xb[1] = xL ^ xR;   // combine(1)
            c.Xb[2] = xR;
        }
    }
    __syncthreads();
}

__global__ void __launch_bounds__(THREADS, 1)
sc_main(const float* r_in,
        const float* Wc2, const float* bc2,
        const float* Wb2, const float* bb2,
        float* out)
{
    extern __shared__ __align__(16) char smraw[];
    Ctx c;
    c.hs  = (u64*)smraw;                     // 64 KB
    c.zs  = c.hs + 32 * 256;                 // 64 KB
    c.red = (float*)(c.zs + 32 * 256);       // 16 KB
    c.nh  = c.red + 4096;
    c.nbp = c.nh + 256;
    c.nx  = (int*)(c.nbp + 256);
    c.b = blockIdx.x;
    c.Eb   = g_E   + c.b * 511 * DD;
    c.BPb  = g_BP  + c.b * 255 * HH;
    c.Xb   = g_X   + c.b * 511;
    c.U1Hb = g_U1H + c.b * 256;
    c.Wc2 = Wc2; c.bc2 = bc2;
    c.Wb2 = Wb2; c.bb2 = bb2;
    c.r_in  = r_in;
    c.u_out = out + 2 * SEC;
    c.p_out = out + 3 * SEC;

    for (int l = 8; l >= 2; l--) check_stage(c, l);
    for (int n = 0; n < 128; n++) {
        node1(c, n);
        if (n == 127) break;
        int l = 2;
        while ((n >> (l - 2)) & 1) { combine_stage(c, l); l++; }
        bit_stage(c, l);
        for (int ld = l - 1; ld >= 2; ld--) check_stage(c, ld);
    }
    for (int l = 2; l <= 8; l++) combine_stage(c, l);

    int* X8 = c.Xb + 255;
    for (int i = threadIdx.x; i < NBLK_C; i += THREADS)
        out[c.b * NBLK_C + i] = (float)X8[i];
}

// ---- per-batch init ----
__global__ void sc_setup(const int* info_bits, const float* r_in, const int* info_set,
                         const float* E_obs, float* out)
{
    int b = blockIdx.x, t = threadIdx.x;
    for (int j = t; j < NBLK_C; j += blockDim.x) {
        g_fenc[b * NBLK_C + j] = 2;
        out[1 * SEC + b * NBLK_C + j] = 1.0f;
        out[4 * SEC + b * NBLK_C + j] = r_in[b * NBLK_C + j];
    }
    __syncthreads();
    for (int k = t; k < 128; k += blockDim.x) {
        int pos = info_set[k];
        g_fenc[b * NBLK_C + pos] = info_bits[b * 128 + k];
        out[1 * SEC + b * NBLK_C + pos] = 2.0f;
    }
    for (int idx = t; idx < 256 * DD; idx += blockDim.x) {
        int i = idx >> 7, k = idx & (DD - 1);
        g_E[b * 511 * DD + (255 + i) * DD + k] = E_obs[2 * DD + k];
    }
}

// ---- parallel weight prep ----
__global__ void sc_prep(const float* Wc1, const float* bc1,
                        const float* Wb1, const float* bb1,
                        const float* E_lab,
                        const float* Wc2, const float* bc2,
                        const float* Wb2, const float* bb2,
                        const float* Wl, const float* bl)
{
    int tid = blockIdx.x * blockDim.x + threadIdx.x;   // 64*512 = 32768 threads
    {   // g_Wf: 32768 float4 copies
        int k = tid >> 7, c4 = (tid & 127) * 4;
        float4 v;
        if (c4 < 256) v = *((const float4*)&Wc1[k * 256 + c4]);
        else          v = *((const float4*)&Wb1[k * 256 + (c4 - 256)]);
        *((float4*)&g_Wf[k * 512 + c4]) = v;
    }
    if (tid < 512) g_bf[tid] = (tid < 256) ? bc1[tid] : bb1[tid - 256];
    if (tid >= 512 && tid < 1024) {
        int cidx = tid - 512;
        const float* W2 = (cidx < 256) ? Wc2 : Wb2;
        int k = cidx & 255;
        float s = 0.f;
        for (int d = 0; d < 128; d++) s += W2[k * 128 + d] * Wl[d];
        g_w2l[cidx] = s;
    }
    if (tid >= 1024 && tid < 1536) {
        int cidx = tid - 1024; int u = cidx >> 8, j = cidx & 255;
        float s = 0.f;
        for (int d = 0; d < 128; d++) s += E_lab[u * 128 + d] * Wb1[(256 + d) * 256 + j];
        g_emb[u * HH + j] = s;
    }
    if (tid == 1536 || tid == 1537) {
        int u = tid - 1536;
        const float* b2 = u ? bb2 : bc2;
        float s = bl[0];
        for (int d = 0; d < 128; d++) s += b2[d] * Wl[d];
        g_pbias[u] = s;
    }
}

extern "C" void kernel_launch(void* const* d_in, const int* in_sizes, int n_in,
                              void* d_out, int out_size)
{
    const int*   info_bits = (const int*)  d_in[0];
    const float* r_in      = (const float*)d_in[1];
    const int*   info_set  = (const int*)  d_in[2];
    const float* E_obs     = (const float*)d_in[3];
    const float* E_lab     = (const float*)d_in[4];
    const float* Wc1 = (const float*)d_in[5];
    const float* bc1 = (const float*)d_in[6];
    const float* Wc2 = (const float*)d_in[7];
    const float* bc2 = (const float*)d_in[8];
    const float* Wb1 = (const float*)d_in[9];
    const float* bb1 = (const float*)d_in[10];
    const float* Wb2 = (const float*)d_in[11];
    const float* bb2 = (const float*)d_in[12];
    const float* Wl  = (const float*)d_in[13];
    const float* bl  = (const float*)d_in[14];
    float* out = (float*)d_out;

    const int smem = (32 * 256 * 8) * 2 + 4096 * 4 + 2 * 256 * 4 + 16;  // ~147.5 KB
    cudaFuncSetAttribute(sc_main, cudaFuncAttributeMaxDynamicSharedMemorySize, smem);

    sc_prep<<<64, 512>>>(Wc1, bc1, Wb1, bb1, E_lab, Wc2, bc2, Wb2, bb2, Wl, bl);
    sc_setup<<<BATCH, 256>>>(info_bits, r_in, info_set, E_obs, out);
    sc_main<<<BATCH, THREADS, smem>>>(r_in, Wc2, bc2, Wb2, bb2, out);
}